// round 13
// baseline (speedup 1.0000x reference)
#include <cuda_runtime.h>
#include <cuda_fp16.h>
#include <mma.h>

using namespace nvcuda;

#define IN_SIZE 128
#define HD 128        // NUM_HEADS * OUT_SIZE = 4*32
#define EPT 32        // edges per thread in rowptr kernel (8 x int4)
#define AS 136        // fp16 smem row stride for wmma
#define GEMM_SMEM ((128 * AS * 2) * 2)   // A + B tiles, fp16 (~68KB)
#define PERSIST_BLOCKS (148 * 5)

// Scratch (device globals — no allocation allowed)
__device__ __half g_hh[(size_t)50000 * HD];  // projected features fp16
__device__ int    g_rowstart[50001];         // CSR row pointer
__device__ int    g_counter;                 // work-stealing cursor

// ---------------------------------------------------------------------------
// helpers
// ---------------------------------------------------------------------------
__device__ __forceinline__ uint2 f4_to_h4(float4 v)
{
    uint2 o;
    *reinterpret_cast<__half2*>(&o.x) = __floats2half2_rn(v.x, v.y);
    *reinterpret_cast<__half2*>(&o.y) = __floats2half2_rn(v.z, v.w);
    return o;
}
__device__ __forceinline__ float ex2(float x)
{
    float r;
    asm("ex2.approx.ftz.f32 %0, %1;" : "=f"(r) : "f"(x));
    return r;
}
__device__ __forceinline__ void ffma2(unsigned long long& d,
                                      unsigned long long a,
                                      unsigned long long b)
{
    asm("fma.rn.f32x2 %0, %1, %2, %0;" : "+l"(d) : "l"(a), "l"(b));
}
__device__ __forceinline__ unsigned long long pack2(float x, float y)
{
    unsigned long long r;
    asm("mov.b64 %0, {%1, %2};" : "=l"(r) : "f"(x), "f"(y));
    return r;
}
__device__ __forceinline__ unsigned long long pack_dup(float x)
{
    unsigned long long r;
    asm("mov.b64 %0, {%1, %1};" : "=l"(r) : "f"(x));
    return r;
}
__device__ __forceinline__ float2 unpack2(unsigned long long v)
{
    float2 f;
    asm("mov.b64 {%0, %1}, %2;" : "=f"(f.x), "=f"(f.y) : "l"(v));
    return f;
}
// 4 halves -> two packed f32x2 (converted ONCE, reused for dot and acc)
__device__ __forceinline__ ulonglong2 h4_to_p2(uint2 u)
{
    const float2 f0 = __half22float2(*reinterpret_cast<const __half2*>(&u.x));
    const float2 f1 = __half22float2(*reinterpret_cast<const __half2*>(&u.y));
    ulonglong2 r;
    r.x = pack2(f0.x, f0.y);
    r.y = pack2(f1.x, f1.y);
    return r;
}

// ---------------------------------------------------------------------------
// Kernel 1: row pointer by boundary scatter over sorted dst. EPT=32 via
// 8 int4 loads/thread. No smem -> full occupancy, ~2 waves. Also resets
// the work-stealing counter.
// ---------------------------------------------------------------------------
__global__ void rowptr_kernel(const int* __restrict__ dst, int E, int N)
{
    if (blockIdx.x == 0 && threadIdx.x == 0) g_counter = 0;

    const int g  = blockIdx.x * blockDim.x + threadIdx.x;
    const int e0 = g * EPT;
    if (e0 >= E) return;

    int last = (e0 == 0) ? -1 : __ldg(&dst[e0 - 1]);
#pragma unroll
    for (int j4 = 0; j4 < EPT / 4; j4++) {
        const int e = e0 + j4 * 4;
        int4 d4;
        if (e + 3 < E) {
            d4 = *(const int4*)&dst[e];
        } else {
            d4.x = (e     < E) ? __ldg(&dst[e])     : last;
            d4.y = (e + 1 < E) ? __ldg(&dst[e + 1]) : d4.x;
            d4.z = (e + 2 < E) ? __ldg(&dst[e + 2]) : d4.y;
            d4.w = (e + 3 < E) ? __ldg(&dst[e + 3]) : d4.z;
        }
        for (int v = last + 1;  v <= d4.x; v++) g_rowstart[v] = e;
        for (int v = d4.x + 1;  v <= d4.y; v++) g_rowstart[v] = e + 1;
        for (int v = d4.y + 1;  v <= d4.z; v++) g_rowstart[v] = e + 2;
        for (int v = d4.z + 1;  v <= d4.w; v++) g_rowstart[v] = e + 3;
        last = d4.w;
    }
    if (e0 + EPT >= E) {
        for (int v = last + 1; v <= N; v++) g_rowstart[v] = E;
    }
}

// ---------------------------------------------------------------------------
// Kernel 2: h = feat @ W via HMMA (128x128 tile, 256 thr, full K=128 in one
// fp16 smem stage). Epilogue stores fp16 g_hh (halves edge-kernel L2 bytes).
// ---------------------------------------------------------------------------
__global__ void __launch_bounds__(256) proj_gemm_kernel(
    const float* __restrict__ feat, const float* __restrict__ W, int N)
{
    extern __shared__ __half smem[];
    __half* As = smem;                 // [128][AS]
    __half* Bs = smem + 128 * AS;      // [128][AS]

    const int t    = threadIdx.x;
    const int lane = t & 31;
    const int w    = t >> 5;
    const int r0   = blockIdx.x * 128;

    {
        const int row  = t >> 1;
        const int colb = (t & 1) * 64;
        const int ra   = min(r0 + row, N - 1);
#pragma unroll
        for (int i = 0; i < 16; i++) {
            const float4 fa = *(const float4*)&feat[(size_t)ra * IN_SIZE + colb + i * 4];
            *(uint2*)&As[row * AS + colb + i * 4] = f4_to_h4(fa);
            const float4 fb = *(const float4*)&W[row * HD + colb + i * 4];
            *(uint2*)&Bs[row * AS + colb + i * 4] = f4_to_h4(fb);
        }
    }
    __syncthreads();

    const int warp_row = (w & 3) * 32;
    const int warp_col = (w >> 2) * 64;

    wmma::fragment<wmma::accumulator, 16, 16, 16, float> acc[2][4];
#pragma unroll
    for (int i = 0; i < 2; i++)
#pragma unroll
        for (int j = 0; j < 4; j++)
            wmma::fill_fragment(acc[i][j], 0.f);

#pragma unroll
    for (int k0 = 0; k0 < 128; k0 += 16) {
        wmma::fragment<wmma::matrix_a, 16, 16, 16, __half, wmma::row_major> af[2];
        wmma::fragment<wmma::matrix_b, 16, 16, 16, __half, wmma::row_major> bf[4];
#pragma unroll
        for (int i = 0; i < 2; i++)
            wmma::load_matrix_sync(af[i], &As[(warp_row + i * 16) * AS + k0], AS);
#pragma unroll
        for (int j = 0; j < 4; j++)
            wmma::load_matrix_sync(bf[j], &Bs[k0 * AS + warp_col + j * 16], AS);
#pragma unroll
        for (int i = 0; i < 2; i++)
#pragma unroll
            for (int j = 0; j < 4; j++)
                wmma::mma_sync(acc[i][j], af[i], bf[j], acc[i][j]);
    }

    __syncthreads();
    float* ep = (float*)smem + w * (32 * 64);
#pragma unroll
    for (int i = 0; i < 2; i++)
#pragma unroll
        for (int j = 0; j < 4; j++)
            wmma::store_matrix_sync(&ep[i * 16 * 64 + j * 16], acc[i][j], 64,
                                    wmma::mem_row_major);
    __syncwarp();

#pragma unroll
    for (int it = 0; it < 16; it++) {
        const int idx = it * 32 + lane;
        const int row = idx >> 4;
        const int c4  = (idx & 15) * 4;
        const int rg  = r0 + warp_row + row;
        if (rg < N) {
            const float4 v = *(const float4*)&ep[row * 64 + c4];
            *(uint2*)&g_hh[(size_t)rg * HD + warp_col + c4] = f4_to_h4(v);
        }
    }
}

// ---------------------------------------------------------------------------
// Kernel 3: fused edge phase — persistent warps, work-stealing one node per
// atomicAdd. fp16 gather (LDG.64/lane = half the L2 bytes of fp32), ONE
// conversion per edge shared by dot and accumulate, packed f32x2 math,
// 4-edge unroll for MLP against L2 latency.
// ---------------------------------------------------------------------------
__global__ void __launch_bounds__(256, 5) edge_warp_kernel(
    const int* __restrict__ src, float* __restrict__ out, int N)
{
    const int l = threadIdx.x & 31;
    const float C = 1.4426950408889634f * 0.17677669529663689f; // log2e/sqrt(32)

    for (;;) {
        int v;
        if (l == 0) v = atomicAdd(&g_counter, 1);
        v = __shfl_sync(0xffffffffu, v, 0);
        if (v >= N) return;

        const int start = g_rowstart[v];
        const int end   = g_rowstart[v + 1];
        float4* outp = (float4*)&out[(size_t)v * HD + 4 * l];

        if (start >= end) {
            *outp = make_float4(0.f, 0.f, 0.f, 0.f);
            continue;
        }

        // dst row, converted + pre-scaled once
        const ulonglong2 hvp = h4_to_p2(*(const uint2*)&g_hh[(size_t)v * HD + 4 * l]);
        const float2 h0 = unpack2(hvp.x);
        const float2 h1 = unpack2(hvp.y);
        const unsigned long long hp0 = pack2(h0.x * C, h0.y * C);
        const unsigned long long hp1 = pack2(h1.x * C, h1.y * C);

        float sA = 0.f, sB = 0.f;
        unsigned long long accA0 = 0ull, accA1 = 0ull;
        unsigned long long accB0 = 0ull, accB1 = 0ull;

        int i = start;
        for (; i + 4 <= end; i += 4) {
            const int s0 = __ldg(&src[i]);
            const int s1 = __ldg(&src[i + 1]);
            const int s2 = __ldg(&src[i + 2]);
            const int s3 = __ldg(&src[i + 3]);
            const uint2 au = *(const uint2*)&g_hh[(size_t)s0 * HD + 4 * l];
            const uint2 bu = *(const uint2*)&g_hh[(size_t)s1 * HD + 4 * l];
            const uint2 cu = *(const uint2*)&g_hh[(size_t)s2 * HD + 4 * l];
            const uint2 du = *(const uint2*)&g_hh[(size_t)s3 * HD + 4 * l];

            // convert once; reuse for dot and acc
            const ulonglong2 ap = h4_to_p2(au);
            const ulonglong2 bp = h4_to_p2(bu);
            const ulonglong2 cp = h4_to_p2(cu);
            const ulonglong2 dp = h4_to_p2(du);

            unsigned long long da = 0ull, db = 0ull, dc = 0ull, dd = 0ull;
            ffma2(da, ap.x, hp0);  ffma2(db, bp.x, hp0);
            ffma2(dc, cp.x, hp0);  ffma2(dd, dp.x, hp0);
            ffma2(da, ap.y, hp1);  ffma2(db, bp.y, hp1);
            ffma2(dc, cp.y, hp1);  ffma2(dd, dp.y, hp1);

            const float2 fa = unpack2(da);
            const float2 fb = unpack2(db);
            const float2 fc = unpack2(dc);
            const float2 fd = unpack2(dd);
            float pa = fa.x + fa.y;
            float pb = fb.x + fb.y;
            float pc = fc.x + fc.y;
            float pd = fd.x + fd.y;

            pa += __shfl_xor_sync(0xffffffffu, pa, 1);
            pb += __shfl_xor_sync(0xffffffffu, pb, 1);
            pc += __shfl_xor_sync(0xffffffffu, pc, 1);
            pd += __shfl_xor_sync(0xffffffffu, pd, 1);
            pa += __shfl_xor_sync(0xffffffffu, pa, 2);
            pb += __shfl_xor_sync(0xffffffffu, pb, 2);
            pc += __shfl_xor_sync(0xffffffffu, pc, 2);
            pd += __shfl_xor_sync(0xffffffffu, pd, 2);
            pa += __shfl_xor_sync(0xffffffffu, pa, 4);
            pb += __shfl_xor_sync(0xffffffffu, pb, 4);
            pc += __shfl_xor_sync(0xffffffffu, pc, 4);
            pd += __shfl_xor_sync(0xffffffffu, pd, 4);

            const float wa = ex2(pa);
            const float wb = ex2(pb);
            const float wc = ex2(pc);
            const float wd = ex2(pd);
            sA += wa + wc;
            sB += wb + wd;

            const unsigned long long wda = pack_dup(wa);
            const unsigned long long wdb = pack_dup(wb);
            const unsigned long long wdc = pack_dup(wc);
            const unsigned long long wdd = pack_dup(wd);
            ffma2(accA0, wda, ap.x);  ffma2(accA1, wda, ap.y);
            ffma2(accB0, wdb, bp.x);  ffma2(accB1, wdb, bp.y);
            ffma2(accA0, wdc, cp.x);  ffma2(accA1, wdc, cp.y);
            ffma2(accB0, wdd, dp.x);  ffma2(accB1, wdd, dp.y);
        }
        for (; i < end; i++) {
            const int s0 = __ldg(&src[i]);
            const ulonglong2 ap =
                h4_to_p2(*(const uint2*)&g_hh[(size_t)s0 * HD + 4 * l]);
            unsigned long long da = 0ull;
            ffma2(da, ap.x, hp0);
            ffma2(da, ap.y, hp1);
            const float2 fa = unpack2(da);
            float p = fa.x + fa.y;
            p += __shfl_xor_sync(0xffffffffu, p, 1);
            p += __shfl_xor_sync(0xffffffffu, p, 2);
            p += __shfl_xor_sync(0xffffffffu, p, 4);
            const float wt = ex2(p);
            sA += wt;
            const unsigned long long wdt = pack_dup(wt);
            ffma2(accA0, wdt, ap.x);
            ffma2(accA1, wdt, ap.y);
        }

        const float inv = 1.f / (sA + sB);
        const float2 a0 = unpack2(accA0);
        const float2 a1 = unpack2(accA1);
        const float2 b0 = unpack2(accB0);
        const float2 b1 = unpack2(accB1);
        *outp = make_float4((a0.x + b0.x) * inv,
                            (a0.y + b0.y) * inv,
                            (a1.x + b1.x) * inv,
                            (a1.y + b1.y) * inv);
    }
}

// ---------------------------------------------------------------------------
// Launch
// ---------------------------------------------------------------------------
extern "C" void kernel_launch(void* const* d_in, const int* in_sizes, int n_in,
                              void* d_out, int out_size)
{
    const float* feat = (const float*)d_in[0];
    const int*   src  = (const int*)d_in[1];
    const int*   dst  = (const int*)d_in[2];
    const float* W    = (const float*)d_in[3];
    float*       out  = (float*)d_out;

    const int N = in_sizes[0] / IN_SIZE;   // 50000
    const int E = in_sizes[1];             // 1600000

    static bool attr_done = false;
    if (!attr_done) {
        cudaFuncSetAttribute(proj_gemm_kernel,
                             cudaFuncAttributeMaxDynamicSharedMemorySize,
                             GEMM_SMEM);
        attr_done = true;
    }

    rowptr_kernel<<<(E / EPT + 255) / 256, 256>>>(dst, E, N);
    proj_gemm_kernel<<<(N + 127) / 128, 256, GEMM_SMEM>>>(feat, W, N);

    int nb = (N + 7) / 8;
    if (nb > PERSIST_BLOCKS) nb = PERSIST_BLOCKS;
    edge_warp_kernel<<<nb, 256>>>(src, out, N);
}

// round 14
// speedup vs baseline: 1.0651x; 1.0651x over previous
#include <cuda_runtime.h>
#include <cuda_fp16.h>
#include <mma.h>

using namespace nvcuda;

#define IN_SIZE 128
#define HD 128        // NUM_HEADS * OUT_SIZE = 4*32
#define AS 136        // fp16 smem row stride for wmma
#define GEMM_SMEM ((128 * AS * 2) * 2)   // A + B tiles, fp16 (~68KB)
#define PERSIST_BLOCKS (148 * 4)

// Scratch (device globals — no allocation allowed)
__device__ __half g_hh[(size_t)50000 * HD];  // projected features fp16
__device__ int    g_rowstart[50001];         // CSR row pointer
__device__ int    g_counter;                 // work-stealing cursor

// ---------------------------------------------------------------------------
// helpers
// ---------------------------------------------------------------------------
__device__ __forceinline__ uint2 f4_to_h4(float4 v)
{
    uint2 o;
    *reinterpret_cast<__half2*>(&o.x) = __floats2half2_rn(v.x, v.y);
    *reinterpret_cast<__half2*>(&o.y) = __floats2half2_rn(v.z, v.w);
    return o;
}
__device__ __forceinline__ float ex2(float x)
{
    float r;
    asm("ex2.approx.ftz.f32 %0, %1;" : "=f"(r) : "f"(x));
    return r;
}
__device__ __forceinline__ void ffma2(unsigned long long& d,
                                      unsigned long long a,
                                      unsigned long long b)
{
    asm("fma.rn.f32x2 %0, %1, %2, %0;" : "+l"(d) : "l"(a), "l"(b));
}
__device__ __forceinline__ unsigned long long pack2(float x, float y)
{
    unsigned long long r;
    asm("mov.b64 %0, {%1, %2};" : "=l"(r) : "f"(x), "f"(y));
    return r;
}
__device__ __forceinline__ unsigned long long pack_dup(float x)
{
    unsigned long long r;
    asm("mov.b64 %0, {%1, %1};" : "=l"(r) : "f"(x));
    return r;
}
__device__ __forceinline__ float2 unpack2(unsigned long long v)
{
    float2 f;
    asm("mov.b64 {%0, %1}, %2;" : "=f"(f.x), "=f"(f.y) : "l"(v));
    return f;
}
// 4 halves -> two packed f32x2 (converted ONCE, reused for dot and acc)
__device__ __forceinline__ ulonglong2 h4_to_p2(uint2 u)
{
    const float2 f0 = __half22float2(*reinterpret_cast<const __half2*>(&u.x));
    const float2 f1 = __half22float2(*reinterpret_cast<const __half2*>(&u.y));
    ulonglong2 r;
    r.x = pack2(f0.x, f0.y);
    r.y = pack2(f1.x, f1.y);
    return r;
}

// ---------------------------------------------------------------------------
// Kernel 1: row pointer by boundary scatter over sorted dst (EPT=4, int4).
// Also resets the work-stealing counter.
// ---------------------------------------------------------------------------
__global__ void rowptr_kernel(const int* __restrict__ dst, int E, int N)
{
    if (blockIdx.x == 0 && threadIdx.x == 0) g_counter = 0;

    const int g  = blockIdx.x * blockDim.x + threadIdx.x;
    const int e0 = g * 4;
    if (e0 >= E) return;

    int4 d4;
    if (e0 + 3 < E) {
        d4 = *(const int4*)&dst[e0];
    } else {
        d4.x = dst[e0];
        d4.y = (e0 + 1 < E) ? dst[e0 + 1] : d4.x;
        d4.z = (e0 + 2 < E) ? dst[e0 + 2] : d4.y;
        d4.w = (e0 + 3 < E) ? dst[e0 + 3] : d4.z;
    }
    const int prev = (e0 == 0) ? -1 : __ldg(&dst[e0 - 1]);

    for (int v = prev + 1;  v <= d4.x; v++) g_rowstart[v] = e0;
    for (int v = d4.x + 1;  v <= d4.y; v++) g_rowstart[v] = e0 + 1;
    for (int v = d4.y + 1;  v <= d4.z; v++) g_rowstart[v] = e0 + 2;
    for (int v = d4.z + 1;  v <= d4.w; v++) g_rowstart[v] = e0 + 3;

    if (e0 + 4 >= E) {
        for (int v = d4.w + 1; v <= N; v++) g_rowstart[v] = E;
    }
}

// ---------------------------------------------------------------------------
// Kernel 2: h = feat @ W via HMMA (128x128 tile, 256 thr, full K=128 in one
// fp16 smem stage). Epilogue stores fp16 g_hh.
// ---------------------------------------------------------------------------
__global__ void __launch_bounds__(256) proj_gemm_kernel(
    const float* __restrict__ feat, const float* __restrict__ W, int N)
{
    extern __shared__ __half smem[];
    __half* As = smem;                 // [128][AS]
    __half* Bs = smem + 128 * AS;      // [128][AS]

    const int t    = threadIdx.x;
    const int lane = t & 31;
    const int w    = t >> 5;
    const int r0   = blockIdx.x * 128;

    {
        const int row  = t >> 1;
        const int colb = (t & 1) * 64;
        const int ra   = min(r0 + row, N - 1);
#pragma unroll
        for (int i = 0; i < 16; i++) {
            const float4 fa = *(const float4*)&feat[(size_t)ra * IN_SIZE + colb + i * 4];
            *(uint2*)&As[row * AS + colb + i * 4] = f4_to_h4(fa);
            const float4 fb = *(const float4*)&W[row * HD + colb + i * 4];
            *(uint2*)&Bs[row * AS + colb + i * 4] = f4_to_h4(fb);
        }
    }
    __syncthreads();

    const int warp_row = (w & 3) * 32;
    const int warp_col = (w >> 2) * 64;

    wmma::fragment<wmma::accumulator, 16, 16, 16, float> acc[2][4];
#pragma unroll
    for (int i = 0; i < 2; i++)
#pragma unroll
        for (int j = 0; j < 4; j++)
            wmma::fill_fragment(acc[i][j], 0.f);

#pragma unroll
    for (int k0 = 0; k0 < 128; k0 += 16) {
        wmma::fragment<wmma::matrix_a, 16, 16, 16, __half, wmma::row_major> af[2];
        wmma::fragment<wmma::matrix_b, 16, 16, 16, __half, wmma::row_major> bf[4];
#pragma unroll
        for (int i = 0; i < 2; i++)
            wmma::load_matrix_sync(af[i], &As[(warp_row + i * 16) * AS + k0], AS);
#pragma unroll
        for (int j = 0; j < 4; j++)
            wmma::load_matrix_sync(bf[j], &Bs[k0 * AS + warp_col + j * 16], AS);
#pragma unroll
        for (int i = 0; i < 2; i++)
#pragma unroll
            for (int j = 0; j < 4; j++)
                wmma::mma_sync(acc[i][j], af[i], bf[j], acc[i][j]);
    }

    __syncthreads();
    float* ep = (float*)smem + w * (32 * 64);
#pragma unroll
    for (int i = 0; i < 2; i++)
#pragma unroll
        for (int j = 0; j < 4; j++)
            wmma::store_matrix_sync(&ep[i * 16 * 64 + j * 16], acc[i][j], 64,
                                    wmma::mem_row_major);
    __syncwarp();

#pragma unroll
    for (int it = 0; it < 16; it++) {
        const int idx = it * 32 + lane;
        const int row = idx >> 4;
        const int c4  = (idx & 15) * 4;
        const int rg  = r0 + warp_row + row;
        if (rg < N) {
            const float4 v = *(const float4*)&ep[row * 64 + c4];
            *(uint2*)&g_hh[(size_t)rg * HD + warp_col + c4] = f4_to_h4(v);
        }
    }
}

// ---------------------------------------------------------------------------
// Kernel 3: fused edge phase — persistent warps, work-stealing. fp16 gather
// (LDG.64/lane), single convert per edge, packed f32x2 math. 8-edge unroll:
// all 8 gathers issued up front, compute in two 4-edge half-batches so the
// first half's ~60 instr of compute hides the second half's L2 latency.
// ---------------------------------------------------------------------------
__global__ void __launch_bounds__(256, 4) edge_warp_kernel(
    const int* __restrict__ src, float* __restrict__ out, int N)
{
    const int l = threadIdx.x & 31;
    const float C = 1.4426950408889634f * 0.17677669529663689f; // log2e/sqrt(32)

    for (;;) {
        int v;
        if (l == 0) v = atomicAdd(&g_counter, 1);
        v = __shfl_sync(0xffffffffu, v, 0);
        if (v >= N) return;

        const int start = g_rowstart[v];
        const int end   = g_rowstart[v + 1];
        float4* outp = (float4*)&out[(size_t)v * HD + 4 * l];

        if (start >= end) {
            *outp = make_float4(0.f, 0.f, 0.f, 0.f);
            continue;
        }

        // dst row, converted + pre-scaled once
        const ulonglong2 hvp = h4_to_p2(*(const uint2*)&g_hh[(size_t)v * HD + 4 * l]);
        const float2 h0 = unpack2(hvp.x);
        const float2 h1 = unpack2(hvp.y);
        const unsigned long long hp0 = pack2(h0.x * C, h0.y * C);
        const unsigned long long hp1 = pack2(h1.x * C, h1.y * C);

        float sA = 0.f, sB = 0.f;
        unsigned long long accA0 = 0ull, accA1 = 0ull;
        unsigned long long accB0 = 0ull, accB1 = 0ull;

#define EDGE_ONE(srcidx)                                                    \
    do {                                                                    \
        const ulonglong2 ap =                                               \
            h4_to_p2(*(const uint2*)&g_hh[(size_t)(srcidx) * HD + 4 * l]);  \
        unsigned long long da = 0ull;                                       \
        ffma2(da, ap.x, hp0);                                               \
        ffma2(da, ap.y, hp1);                                               \
        const float2 fa = unpack2(da);                                      \
        float p = fa.x + fa.y;                                              \
        p += __shfl_xor_sync(0xffffffffu, p, 1);                            \
        p += __shfl_xor_sync(0xffffffffu, p, 2);                            \
        p += __shfl_xor_sync(0xffffffffu, p, 4);                            \
        const float wt = ex2(p);                                            \
        sA += wt;                                                           \
        const unsigned long long wdt = pack_dup(wt);                        \
        ffma2(accA0, wdt, ap.x);                                            \
        ffma2(accA1, wdt, ap.y);                                            \
    } while (0)

        int i = start;
        // peel to 4-aligned for int4 src loads
        while (i < end && (i & 3)) { EDGE_ONE(__ldg(&src[i])); i++; }

        for (; i + 8 <= end; i += 8) {
            const int4 sa4 = *(const int4*)&src[i];
            const int4 sb4 = *(const int4*)&src[i + 4];

            // issue all 8 gathers up front
            const uint2 u0 = *(const uint2*)&g_hh[(size_t)sa4.x * HD + 4 * l];
            const uint2 u1 = *(const uint2*)&g_hh[(size_t)sa4.y * HD + 4 * l];
            const uint2 u2 = *(const uint2*)&g_hh[(size_t)sa4.z * HD + 4 * l];
            const uint2 u3 = *(const uint2*)&g_hh[(size_t)sa4.w * HD + 4 * l];
            const uint2 u4 = *(const uint2*)&g_hh[(size_t)sb4.x * HD + 4 * l];
            const uint2 u5 = *(const uint2*)&g_hh[(size_t)sb4.y * HD + 4 * l];
            const uint2 u6 = *(const uint2*)&g_hh[(size_t)sb4.z * HD + 4 * l];
            const uint2 u7 = *(const uint2*)&g_hh[(size_t)sb4.w * HD + 4 * l];

            // ---- half-batch 1: edges 0..3
            {
                const ulonglong2 ap = h4_to_p2(u0);
                const ulonglong2 bp = h4_to_p2(u1);
                const ulonglong2 cp = h4_to_p2(u2);
                const ulonglong2 dp = h4_to_p2(u3);

                unsigned long long da = 0ull, db = 0ull, dc = 0ull, dd = 0ull;
                ffma2(da, ap.x, hp0);  ffma2(db, bp.x, hp0);
                ffma2(dc, cp.x, hp0);  ffma2(dd, dp.x, hp0);
                ffma2(da, ap.y, hp1);  ffma2(db, bp.y, hp1);
                ffma2(dc, cp.y, hp1);  ffma2(dd, dp.y, hp1);

                const float2 fa = unpack2(da);
                const float2 fb = unpack2(db);
                const float2 fc = unpack2(dc);
                const float2 fd = unpack2(dd);
                float pa = fa.x + fa.y;
                float pb = fb.x + fb.y;
                float pc = fc.x + fc.y;
                float pd = fd.x + fd.y;

                pa += __shfl_xor_sync(0xffffffffu, pa, 1);
                pb += __shfl_xor_sync(0xffffffffu, pb, 1);
                pc += __shfl_xor_sync(0xffffffffu, pc, 1);
                pd += __shfl_xor_sync(0xffffffffu, pd, 1);
                pa += __shfl_xor_sync(0xffffffffu, pa, 2);
                pb += __shfl_xor_sync(0xffffffffu, pb, 2);
                pc += __shfl_xor_sync(0xffffffffu, pc, 2);
                pd += __shfl_xor_sync(0xffffffffu, pd, 2);
                pa += __shfl_xor_sync(0xffffffffu, pa, 4);
                pb += __shfl_xor_sync(0xffffffffu, pb, 4);
                pc += __shfl_xor_sync(0xffffffffu, pc, 4);
                pd += __shfl_xor_sync(0xffffffffu, pd, 4);

                const float wa = ex2(pa);
                const float wb = ex2(pb);
                const float wc = ex2(pc);
                const float wd = ex2(pd);
                sA += wa + wc;
                sB += wb + wd;

                const unsigned long long wda = pack_dup(wa);
                const unsigned long long wdb = pack_dup(wb);
                const unsigned long long wdc = pack_dup(wc);
                const unsigned long long wdd = pack_dup(wd);
                ffma2(accA0, wda, ap.x);  ffma2(accA1, wda, ap.y);
                ffma2(accB0, wdb, bp.x);  ffma2(accB1, wdb, bp.y);
                ffma2(accA0, wdc, cp.x);  ffma2(accA1, wdc, cp.y);
                ffma2(accB0, wdd, dp.x);  ffma2(accB1, wdd, dp.y);
            }
            // ---- half-batch 2: edges 4..7
            {
                const ulonglong2 ap = h4_to_p2(u4);
                const ulonglong2 bp = h4_to_p2(u5);
                const ulonglong2 cp = h4_to_p2(u6);
                const ulonglong2 dp = h4_to_p2(u7);

                unsigned long long da = 0ull, db = 0ull, dc = 0ull, dd = 0ull;
                ffma2(da, ap.x, hp0);  ffma2(db, bp.x, hp0);
                ffma2(dc, cp.x, hp0);  ffma2(dd, dp.x, hp0);
                ffma2(da, ap.y, hp1);  ffma2(db, bp.y, hp1);
                ffma2(dc, cp.y, hp1);  ffma2(dd, dp.y, hp1);

                const float2 fa = unpack2(da);
                const float2 fb = unpack2(db);
                const float2 fc = unpack2(dc);
                const float2 fd = unpack2(dd);
                float pa = fa.x + fa.y;
                float pb = fb.x + fb.y;
                float pc = fc.x + fc.y;
                float pd = fd.x + fd.y;

                pa += __shfl_xor_sync(0xffffffffu, pa, 1);
                pb += __shfl_xor_sync(0xffffffffu, pb, 1);
                pc += __shfl_xor_sync(0xffffffffu, pc, 1);
                pd += __shfl_xor_sync(0xffffffffu, pd, 1);
                pa += __shfl_xor_sync(0xffffffffu, pa, 2);
                pb += __shfl_xor_sync(0xffffffffu, pb, 2);
                pc += __shfl_xor_sync(0xffffffffu, pc, 2);
                pd += __shfl_xor_sync(0xffffffffu, pd, 2);
                pa += __shfl_xor_sync(0xffffffffu, pa, 4);
                pb += __shfl_xor_sync(0xffffffffu, pb, 4);
                pc += __shfl_xor_sync(0xffffffffu, pc, 4);
                pd += __shfl_xor_sync(0xffffffffu, pd, 4);

                const float wa = ex2(pa);
                const float wb = ex2(pb);
                const float wc = ex2(pc);
                const float wd = ex2(pd);
                sA += wa + wc;
                sB += wb + wd;

                const unsigned long long wda = pack_dup(wa);
                const unsigned long long wdb = pack_dup(wb);
                const unsigned long long wdc = pack_dup(wc);
                const unsigned long long wdd = pack_dup(wd);
                ffma2(accA0, wda, ap.x);  ffma2(accA1, wda, ap.y);
                ffma2(accB0, wdb, bp.x);  ffma2(accB1, wdb, bp.y);
                ffma2(accA0, wdc, cp.x);  ffma2(accA1, wdc, cp.y);
                ffma2(accB0, wdd, dp.x);  ffma2(accB1, wdd, dp.y);
            }
        }
        // tail
        for (; i < end; i++) EDGE_ONE(__ldg(&src[i]));
#undef EDGE_ONE

        const float inv = 1.f / (sA + sB);
        const float2 a0 = unpack2(accA0);
        const float2 a1 = unpack2(accA1);
        const float2 b0 = unpack2(accB0);
        const float2 b1 = unpack2(accB1);
        *outp = make_float4((a0.x + b0.x) * inv,
                            (a0.y + b0.y) * inv,
                            (a1.x + b1.x) * inv,
                            (a1.y + b1.y) * inv);
    }
}

// ---------------------------------------------------------------------------
// Launch
// ---------------------------------------------------------------------------
extern "C" void kernel_launch(void* const* d_in, const int* in_sizes, int n_in,
                              void* d_out, int out_size)
{
    const float* feat = (const float*)d_in[0];
    const int*   src  = (const int*)d_in[1];
    const int*   dst  = (const int*)d_in[2];
    const float* W    = (const float*)d_in[3];
    float*       out  = (float*)d_out;

    const int N = in_sizes[0] / IN_SIZE;   // 50000
    const int E = in_sizes[1];             // 1600000

    static bool attr_done = false;
    if (!attr_done) {
        cudaFuncSetAttribute(proj_gemm_kernel,
                             cudaFuncAttributeMaxDynamicSharedMemorySize,
                             GEMM_SMEM);
        attr_done = true;
    }

    rowptr_kernel<<<(E / 4 + 255) / 256, 256>>>(dst, E, N);
    proj_gemm_kernel<<<(N + 127) / 128, 256, GEMM_SMEM>>>(feat, W, N);

    int nb = (N + 7) / 8;
    if (nb > PERSIST_BLOCKS) nb = PERSIST_BLOCKS;
    edge_warp_kernel<<<nb, 256>>>(src, out, N);
}